// round 9
// baseline (speedup 1.0000x reference)
#include <cuda_runtime.h>
#include <cuda_bf16.h>
#include <math.h>
#include <stdint.h>

// Problem constants
#define D_MODEL 1024
#define D_STATE 16
#define D_CONV  4
#define D_INNER 2048
#define DT_RANK 64
#define BATCH   4
#define LENGTH  2048
#define ML      (BATCH * LENGTH)          // 8192 rows
#define DBC_N   (DT_RANK + 2 * D_STATE)   // 96

// ---------------- scratch (static __device__, no allocations) ----------------
__device__ float g_xz[ML * 2 * D_INNER];     // 8192 x 4096 (fp32)
__device__ float g_xc[ML * D_INNER];         // 8192 x 2048 (fp32, for scan)
__device__ float g_dbc[ML * DBC_N];          // 8192 x 96
__device__ float g_delta[ML * D_INNER];      // 8192 x 2048

// bf16 hi/lo operand buffers
__device__ __nv_bfloat16 g_xhi [ML * D_MODEL],       g_xlo [ML * D_MODEL];
__device__ __nv_bfloat16 g_winhi[2*D_INNER*D_MODEL], g_winlo[2*D_INNER*D_MODEL];
__device__ __nv_bfloat16 g_wxhi[DBC_N * D_INNER],    g_wxlo[DBC_N * D_INNER];
__device__ __nv_bfloat16 g_wdthi[D_INNER*DT_RANK],   g_wdtlo[D_INNER*DT_RANK];
__device__ __nv_bfloat16 g_wouthi[D_MODEL*D_INNER],  g_woutlo[D_MODEL*D_INNER];
__device__ __nv_bfloat16 g_xchi[ML * D_INNER],       g_xclo[ML * D_INNER];
__device__ __nv_bfloat16 g_dthi[ML * DT_RANK],       g_dtlo[ML * DT_RANK];
__device__ __nv_bfloat16 g_yhi [ML * D_INNER],       g_ylo [ML * D_INNER];

// ======================= low-level helpers (base sm_103 ISA only) ============
__device__ __forceinline__ uint32_t smem_to_u32(const void* p) {
    uint32_t a;
    asm("{ .reg .u64 t; cvta.to.shared.u64 t, %1; cvt.u32.u64 %0, t; }"
        : "=r"(a) : "l"(p));
    return a;
}
__device__ __forceinline__ void cp_async16(uint32_t dst, const void* src, bool pred) {
    int sz = pred ? 16 : 0;
    asm volatile("cp.async.cg.shared.global [%0], [%1], 16, %2;"
                 :: "r"(dst), "l"(src), "r"(sz) : "memory");
}
#define CP_COMMIT() asm volatile("cp.async.commit_group;" ::: "memory")
template <int N>
__device__ __forceinline__ void cp_wait() {
    asm volatile("cp.async.wait_group %0;" :: "n"(N) : "memory");
}

__device__ __forceinline__ void ldsm4(uint32_t* r, uint32_t addr) {
    asm volatile("ldmatrix.sync.aligned.m8n8.x4.shared.b16 {%0,%1,%2,%3}, [%4];"
                 : "=r"(r[0]), "=r"(r[1]), "=r"(r[2]), "=r"(r[3]) : "r"(addr));
}
__device__ __forceinline__ void mma16816(float* d, const uint32_t* a, const uint32_t* b) {
    asm volatile(
        "mma.sync.aligned.m16n8k16.row.col.f32.bf16.bf16.f32 "
        "{%0,%1,%2,%3}, {%4,%5,%6,%7}, {%8,%9}, {%0,%1,%2,%3};"
        : "+f"(d[0]), "+f"(d[1]), "+f"(d[2]), "+f"(d[3])
        : "r"(a[0]), "r"(a[1]), "r"(a[2]), "r"(a[3]), "r"(b[0]), "r"(b[1]));
}

// ======================= split-bf16x3 GEMM (mma.sync) ========================
// C[M,N] = A[M,K] * B[N,K]^T  via  hi*Hi + hi*Lo + lo*Hi, fp32 accumulate.
// CTA tile 128x128, BK=32, 8 warps (warp tile 32x64), 4-stage cp.async pipeline
// with partial waits (wait_group 2 steady-state -> 3 k-blocks of load slack).
// smem rows padded to 40 bf16 (80B) -> conflict-free ldmatrix.
// Modes: 0 plain fp32 C; 1 fp32 C + bf16 hi/lo of cols < hi_ncols; 2 softplus(v+bias).
#define TILE_BYTES  10240                  // 128 rows * 80B
#define STAGE_BYTES (4 * TILE_BYTES)       // Ah, Al, Bh, Bl
#define NSTAGE 4
#define OFF_AH 0
#define OFF_AL TILE_BYTES
#define OFF_BH (2 * TILE_BYTES)
#define OFF_BL (3 * TILE_BYTES)

__device__ __forceinline__ void load_stage(
    uint32_t sb, const __nv_bfloat16* __restrict__ Ahi,
    const __nv_bfloat16* __restrict__ Alo,
    const __nv_bfloat16* __restrict__ Bhi,
    const __nv_bfloat16* __restrict__ Blo,
    int K, int N, int m0, int n0, int kbase, int tid)
{
#pragma unroll
    for (int i = 0; i < 2; i++) {
        const int idx = i * 256 + tid;            // 0..511
        const int r = idx >> 2, seg = idx & 3;
        const size_t ga = (size_t)(m0 + r) * K + kbase + seg * 8;
        const uint32_t da = sb + r * 80 + seg * 16;
        cp_async16(da + OFF_AH, Ahi + ga, true);
        cp_async16(da + OFF_AL, Alo + ga, true);
        const bool v = (n0 + r) < N;
        const size_t gb = (size_t)(n0 + (v ? r : 0)) * K + kbase + seg * 8;
        cp_async16(da + OFF_BH, Bhi + gb, v);
        cp_async16(da + OFF_BL, Blo + gb, v);
    }
}

__global__ __launch_bounds__(256) void gemm_bf16x3(
    const __nv_bfloat16* __restrict__ Ahi, const __nv_bfloat16* __restrict__ Alo,
    const __nv_bfloat16* __restrict__ Bhi, const __nv_bfloat16* __restrict__ Blo,
    int K, int N, int ldc, float* __restrict__ C,
    int mode, const float* __restrict__ bias,
    __nv_bfloat16* __restrict__ hi_out, __nv_bfloat16* __restrict__ lo_out,
    int hi_ld, int hi_ncols)
{
    extern __shared__ char smem[];
    const uint32_t sbase = smem_to_u32(smem);
    const int tid  = threadIdx.x;
    const int wid  = tid >> 5;
    const int lane = tid & 31;
    const int m0 = blockIdx.y * 128;
    const int n0 = blockIdx.x * 128;
    const int wm = wid >> 1;          // 0..3
    const int wn = wid & 1;           // 0..1

    // ldmatrix lane addressing
    const int lr = lane & 7, lg = lane >> 3;       // lg 0..3
    const int a_row = ((lg & 1) << 3) + lr;        // 0..15
    const int a_col = (lg >> 1) << 3;              // 0 or 8 (elements)
    const int b_row = ((lg >> 1) << 3) + lr;       // 0..15
    const int b_col = (lg & 1) << 3;               // 0 or 8

    float acc[2][8][4];
#pragma unroll
    for (int mi = 0; mi < 2; mi++)
#pragma unroll
        for (int nj = 0; nj < 8; nj++)
#pragma unroll
            for (int e = 0; e < 4; e++) acc[mi][nj][e] = 0.f;

    const int KB = K >> 5;    // k-blocks of 32

    // prologue: issue up to NSTAGE-1 stages
#pragma unroll
    for (int s = 0; s < NSTAGE - 1; s++) {
        if (s < KB) {
            load_stage(sbase + s * STAGE_BYTES, Ahi, Alo, Bhi, Blo,
                       K, N, m0, n0, s << 5, tid);
            CP_COMMIT();
        }
    }

    for (int kb = 0; kb < KB; kb++) {
        // wait until stage kb is resident; keep later stages in flight
        const int rem = KB - 1 - kb;   // groups potentially outstanding beyond kb
        if (rem >= 2)      cp_wait<2>();
        else if (rem == 1) cp_wait<1>();
        else               cp_wait<0>();
        __syncthreads();

        // issue stage kb+NSTAGE-1 (its buffer was consumed at iter kb-1)
        const int ks2 = kb + NSTAGE - 1;
        if (ks2 < KB) {
            load_stage(sbase + (ks2 & (NSTAGE - 1)) * STAGE_BYTES,
                       Ahi, Alo, Bhi, Blo, K, N, m0, n0, ks2 << 5, tid);
            CP_COMMIT();
        }

        const uint32_t st = sbase + (kb & (NSTAGE - 1)) * STAGE_BYTES;
#pragma unroll
        for (int ks = 0; ks < 2; ks++) {
            const uint32_t aoff = st + (wm * 32 + a_row) * 80 + (ks * 16 + a_col) * 2;
            const uint32_t boff = st + OFF_BH + (wn * 64 + b_row) * 80 + (ks * 16 + b_col) * 2;
            uint32_t ah[2][4], al[2][4], bh[4][4], bl[4][4];
            ldsm4(ah[0], aoff + OFF_AH);
            ldsm4(ah[1], aoff + OFF_AH + 16 * 80);
            ldsm4(bh[0], boff);
            ldsm4(bh[1], boff + 16 * 80);
            ldsm4(bh[2], boff + 32 * 80);
            ldsm4(bh[3], boff + 48 * 80);
#pragma unroll
            for (int mi = 0; mi < 2; mi++)
#pragma unroll
                for (int nj = 0; nj < 8; nj++)
                    mma16816(acc[mi][nj], ah[mi], &bh[nj >> 1][(nj & 1) * 2]);
            ldsm4(al[0], aoff + OFF_AL);
            ldsm4(al[1], aoff + OFF_AL + 16 * 80);
#pragma unroll
            for (int mi = 0; mi < 2; mi++)
#pragma unroll
                for (int nj = 0; nj < 8; nj++)
                    mma16816(acc[mi][nj], al[mi], &bh[nj >> 1][(nj & 1) * 2]);
            ldsm4(bl[0], boff + TILE_BYTES);
            ldsm4(bl[1], boff + TILE_BYTES + 16 * 80);
            ldsm4(bl[2], boff + TILE_BYTES + 32 * 80);
            ldsm4(bl[3], boff + TILE_BYTES + 48 * 80);
#pragma unroll
            for (int mi = 0; mi < 2; mi++)
#pragma unroll
                for (int nj = 0; nj < 8; nj++)
                    mma16816(acc[mi][nj], ah[mi], &bl[nj >> 1][(nj & 1) * 2]);
        }
        __syncthreads();
    }

    // ----- epilogue -----
    const int rbase = m0 + wm * 32 + (lane >> 2);
    const int cbase = n0 + wn * 64 + (lane & 3) * 2;
#pragma unroll
    for (int mi = 0; mi < 2; mi++) {
#pragma unroll
        for (int e = 0; e < 2; e++) {
            const int row = rbase + mi * 16 + e * 8;
#pragma unroll
            for (int nj = 0; nj < 8; nj++) {
                const int c = cbase + nj * 8;
                if (c >= N) continue;
                float v0 = acc[mi][nj][e * 2 + 0];
                float v1 = acc[mi][nj][e * 2 + 1];
                if (mode == 2) {
                    float t0 = v0 + bias[c];
                    float t1 = v1 + bias[c + 1];
                    v0 = (t0 > 20.f) ? t0 : log1pf(__expf(t0));
                    v1 = (t1 > 20.f) ? t1 : log1pf(__expf(t1));
                }
                *(float2*)(C + (size_t)row * ldc + c) = make_float2(v0, v1);
                if (mode == 1 && c < hi_ncols) {
                    const __nv_bfloat16 h0 = __float2bfloat16(v0);
                    const __nv_bfloat16 h1 = __float2bfloat16(v1);
                    hi_out[(size_t)row * hi_ld + c]     = h0;
                    hi_out[(size_t)row * hi_ld + c + 1] = h1;
                    lo_out[(size_t)row * hi_ld + c]     = __float2bfloat16(v0 - __bfloat162float(h0));
                    lo_out[(size_t)row * hi_ld + c + 1] = __float2bfloat16(v1 - __bfloat162float(h1));
                }
            }
        }
    }
}

// ---------------- fp32 -> bf16 hi/lo conversion ----------------
__global__ __launch_bounds__(256) void cvt_hilo(
    const float* __restrict__ src, __nv_bfloat16* __restrict__ hi,
    __nv_bfloat16* __restrict__ lo, int n)
{
    for (int i = blockIdx.x * 256 + threadIdx.x; i < n; i += gridDim.x * 256) {
        const float v = src[i];
        const __nv_bfloat16 h = __float2bfloat16(v);
        hi[i] = h;
        lo[i] = __float2bfloat16(v - __bfloat162float(h));
    }
}

// ---------------- causal depthwise conv (k=4) + bias + SiLU ----------------
__global__ __launch_bounds__(256) void conv_silu_kernel(
    const float* __restrict__ conv_w, const float* __restrict__ conv_b)
{
    const int d  = blockIdx.x * 256 + threadIdx.x;
    const int l0 = blockIdx.y * 128;
    const int b  = blockIdx.z;

    const float w0 = conv_w[d * 4 + 0], w1 = conv_w[d * 4 + 1];
    const float w2 = conv_w[d * 4 + 2], w3 = conv_w[d * 4 + 3];
    const float bias = conv_b[d];

    const float* in = g_xz + (size_t)(b * LENGTH) * (2 * D_INNER) + d;
    float x0 = 0.f, x1 = 0.f, x2 = 0.f;
    if (l0 >= 3) {
        x0 = in[(size_t)(l0 - 3) * (2 * D_INNER)];
        x1 = in[(size_t)(l0 - 2) * (2 * D_INNER)];
        x2 = in[(size_t)(l0 - 1) * (2 * D_INNER)];
    }
    size_t o = (size_t)(b * LENGTH + l0) * D_INNER + d;
#pragma unroll 4
    for (int l = l0; l < l0 + 128; l++) {
        const float x3 = in[(size_t)l * (2 * D_INNER)];
        float v = fmaf(w0, x0, fmaf(w1, x1, fmaf(w2, x2, fmaf(w3, x3, bias))));
        v = v / (1.f + __expf(-v));
        g_xc[o] = v;
        const __nv_bfloat16 h = __float2bfloat16(v);
        g_xchi[o] = h;
        g_xclo[o] = __float2bfloat16(v - __bfloat162float(h));
        o += D_INNER;
        x0 = x1; x1 = x2; x2 = x3;
    }
}

// ---------------- selective scan + D*x + silu(z) gating (pipelined) ----------
// Single-warp blocks. lane = n_grp*8 + d_sub : 8 d's per warp, 4 states/thread.
// L processed in chunks of 4 with double-buffered register arrays: loads for
// chunk c+1 issue BEFORE the math of chunk c, so L2 latency is hidden.
#define SCAN_CH 4
__global__ __launch_bounds__(32) void scan_kernel(
    const float* __restrict__ A_raw, const float* __restrict__ Dvec)
{
    const int lane = threadIdx.x & 31;
    const int d  = blockIdx.x * 8 + (lane & 7);
    const int n0 = (lane >> 3) * 4;
    const int b  = blockIdx.y;

    const float A0 = -expf(A_raw[(n0 + 0) * D_INNER + d]);
    const float A1 = -expf(A_raw[(n0 + 1) * D_INNER + d]);
    const float A2 = -expf(A_raw[(n0 + 2) * D_INNER + d]);
    const float A3 = -expf(A_raw[(n0 + 3) * D_INNER + d]);
    const float Dv = Dvec[d];

    const int row0 = b * LENGTH;
    const float* dp = g_delta + (size_t)row0 * D_INNER + d;
    const float* xp = g_xc    + (size_t)row0 * D_INNER + d;
    const float* zp = g_xz    + (size_t)row0 * (2 * D_INNER) + D_INNER + d;
    const float4* Bp = (const float4*)(g_dbc + (size_t)row0 * DBC_N + DT_RANK + n0);
    const float4* Cp = (const float4*)(g_dbc + (size_t)row0 * DBC_N + DT_RANK + D_STATE + n0);
    const size_t yo0 = (size_t)row0 * D_INNER + d;

    float  dlt[2][SCAN_CH], xv[2][SCAN_CH], zv[2][SCAN_CH];
    float4 Bv[2][SCAN_CH], Cv[2][SCAN_CH];

    // prologue: load chunk 0 into buffer 0
#pragma unroll
    for (int i = 0; i < SCAN_CH; i++) {
        dlt[0][i] = dp[(size_t)i * D_INNER];
        xv [0][i] = xp[(size_t)i * D_INNER];
        zv [0][i] = zp[(size_t)i * 2 * D_INNER];
        Bv [0][i] = Bp[i * (DBC_N / 4)];
        Cv [0][i] = Cp[i * (DBC_N / 4)];
    }

    float h0 = 0.f, h1 = 0.f, h2 = 0.f, h3 = 0.f;

    const int NCH = LENGTH / SCAN_CH;   // 512
#pragma unroll 2
    for (int c = 0; c < NCH; c++) {
        const int cur = c & 1, nxt = cur ^ 1;
        // ---- issue loads for chunk c+1 (before any math of chunk c) ----
        if (c + 1 < NCH) {
            const size_t lb = (size_t)(c + 1) * SCAN_CH;
#pragma unroll
            for (int i = 0; i < SCAN_CH; i++) {
                dlt[nxt][i] = dp[(lb + i) * D_INNER];
                xv [nxt][i] = xp[(lb + i) * D_INNER];
                zv [nxt][i] = zp[(lb + i) * 2 * D_INNER];
                Bv [nxt][i] = Bp[(lb + i) * (DBC_N / 4)];
                Cv [nxt][i] = Cp[(lb + i) * (DBC_N / 4)];
            }
        }
        // ---- math for chunk c ----
#pragma unroll
        for (int i = 0; i < SCAN_CH; i++) {
            const float dl = dlt[cur][i];
            const float xx = xv[cur][i];
            const float dx = dl * xx;
            const float4 B4 = Bv[cur][i];
            const float4 C4 = Cv[cur][i];
            h0 = fmaf(__expf(dl * A0), h0, B4.x * dx);
            h1 = fmaf(__expf(dl * A1), h1, B4.y * dx);
            h2 = fmaf(__expf(dl * A2), h2, B4.z * dx);
            h3 = fmaf(__expf(dl * A3), h3, B4.w * dx);
            float p = C4.x * h0 + C4.y * h1 + C4.z * h2 + C4.w * h3;
            p += __shfl_xor_sync(0xffffffffu, p, 8);
            p += __shfl_xor_sync(0xffffffffu, p, 16);
            if (n0 == 0) {
                const float zz = zv[cur][i];
                const float sz = zz / (1.f + __expf(-zz));
                const float yv = (p + Dv * xx) * sz;
                const __nv_bfloat16 hb = __float2bfloat16(yv);
                const size_t yo = yo0 + (size_t)(c * SCAN_CH + i) * D_INNER;
                g_yhi[yo] = hb;
                g_ylo[yo] = __float2bfloat16(yv - __bfloat162float(hb));
            }
        }
    }
}

// ---------------- host launch ----------------
extern "C" void kernel_launch(void* const* d_in, const int* in_sizes, int n_in,
                              void* d_out, int out_size)
{
    const float* x      = (const float*)d_in[0];
    const float* W_in   = (const float*)d_in[1];
    const float* conv_w = (const float*)d_in[2];
    const float* conv_b = (const float*)d_in[3];
    const float* W_x    = (const float*)d_in[4];
    const float* W_dt   = (const float*)d_in[5];
    const float* b_dt   = (const float*)d_in[6];
    const float* A_raw  = (const float*)d_in[7];
    const float* Dvec   = (const float*)d_in[8];
    const float* W_out  = (const float*)d_in[9];
    float* out = (float*)d_out;

    float *p_xz, *p_dbc, *p_delta;
    __nv_bfloat16 *p_xhi, *p_xlo, *p_winhi, *p_winlo, *p_wxhi, *p_wxlo;
    __nv_bfloat16 *p_wdthi, *p_wdtlo, *p_wouthi, *p_woutlo;
    __nv_bfloat16 *p_xchi, *p_xclo, *p_dthi, *p_dtlo, *p_yhi, *p_ylo;
    cudaGetSymbolAddress((void**)&p_xz,    g_xz);
    cudaGetSymbolAddress((void**)&p_dbc,   g_dbc);
    cudaGetSymbolAddress((void**)&p_delta, g_delta);
    cudaGetSymbolAddress((void**)&p_xhi,   g_xhi);
    cudaGetSymbolAddress((void**)&p_xlo,   g_xlo);
    cudaGetSymbolAddress((void**)&p_winhi, g_winhi);
    cudaGetSymbolAddress((void**)&p_winlo, g_winlo);
    cudaGetSymbolAddress((void**)&p_wxhi,  g_wxhi);
    cudaGetSymbolAddress((void**)&p_wxlo,  g_wxlo);
    cudaGetSymbolAddress((void**)&p_wdthi, g_wdthi);
    cudaGetSymbolAddress((void**)&p_wdtlo, g_wdtlo);
    cudaGetSymbolAddress((void**)&p_wouthi,g_wouthi);
    cudaGetSymbolAddress((void**)&p_woutlo,g_woutlo);
    cudaGetSymbolAddress((void**)&p_xchi,  g_xchi);
    cudaGetSymbolAddress((void**)&p_xclo,  g_xclo);
    cudaGetSymbolAddress((void**)&p_dthi,  g_dthi);
    cudaGetSymbolAddress((void**)&p_dtlo,  g_dtlo);
    cudaGetSymbolAddress((void**)&p_yhi,   g_yhi);
    cudaGetSymbolAddress((void**)&p_ylo,   g_ylo);

    const int SMEM = NSTAGE * STAGE_BYTES;   // 163840 bytes
    cudaFuncSetAttribute(gemm_bf16x3, cudaFuncAttributeMaxDynamicSharedMemorySize, SMEM);

    // 0) conversions to bf16 hi/lo
    cvt_hilo<<<1024, 256>>>(x,     p_xhi,   p_xlo,   ML * D_MODEL);
    cvt_hilo<<<1024, 256>>>(W_in,  p_winhi, p_winlo, 2 * D_INNER * D_MODEL);
    cvt_hilo<<<256,  256>>>(W_x,   p_wxhi,  p_wxlo,  DBC_N * D_INNER);
    cvt_hilo<<<256,  256>>>(W_dt,  p_wdthi, p_wdtlo, D_INNER * DT_RANK);
    cvt_hilo<<<1024, 256>>>(W_out, p_wouthi,p_woutlo,D_MODEL * D_INNER);

    // 1) xz = x @ W_in^T : [8192,1024] x [4096,1024]^T
    {
        dim3 grid((2 * D_INNER) / 128, ML / 128);
        gemm_bf16x3<<<grid, 256, SMEM>>>(p_xhi, p_xlo, p_winhi, p_winlo,
            D_MODEL, 2 * D_INNER, 2 * D_INNER, p_xz, 0, nullptr, nullptr, nullptr, 0, 0);
    }
    // 2) causal conv + SiLU -> xc (fp32 + hi/lo)
    {
        dim3 grid(D_INNER / 256, LENGTH / 128, BATCH);
        conv_silu_kernel<<<grid, 256>>>(conv_w, conv_b);
    }
    // 3) dbc = xc @ W_x^T : N=96; epilogue also emits dt hi/lo (cols<64)
    {
        dim3 grid(1, ML / 128);
        gemm_bf16x3<<<grid, 256, SMEM>>>(p_xchi, p_xclo, p_wxhi, p_wxlo,
            D_INNER, DBC_N, DBC_N, p_dbc, 1, nullptr, p_dthi, p_dtlo, DT_RANK, DT_RANK);
    }
    // 4) delta = softplus(dt @ W_dt^T + b_dt)
    {
        dim3 grid(D_INNER / 128, ML / 128);
        gemm_bf16x3<<<grid, 256, SMEM>>>(p_dthi, p_dtlo, p_wdthi, p_wdtlo,
            DT_RANK, D_INNER, D_INNER, p_delta, 2, b_dt, nullptr, nullptr, 0, 0);
    }
    // 5) selective scan -> y (bf16 hi/lo), pipelined
    {
        dim3 grid(D_INNER / 8, BATCH);
        scan_kernel<<<grid, 32>>>(A_raw, Dvec);
    }
    // 6) out = y @ W_out^T
    {
        dim3 grid(D_MODEL / 128, ML / 128);
        gemm_bf16x3<<<grid, 256, SMEM>>>(p_yhi, p_ylo, p_wouthi, p_woutlo,
            D_INNER, D_MODEL, D_MODEL, out, 0, nullptr, nullptr, nullptr, 0, 0);
    }
}

// round 11
// speedup vs baseline: 1.2382x; 1.2382x over previous
#include <cuda_runtime.h>
#include <cuda_fp16.h>
#include <math.h>
#include <stdint.h>

// Problem constants
#define D_MODEL 1024
#define D_STATE 16
#define D_CONV  4
#define D_INNER 2048
#define DT_RANK 64
#define BATCH   4
#define LENGTH  2048
#define ML      (BATCH * LENGTH)          // 8192 rows
#define DBC_N   (DT_RANK + 2 * D_STATE)   // 96

// ---------------- scratch (static __device__, no allocations) ----------------
__device__ float g_xz[ML * 2 * D_INNER];     // 8192 x 4096 (fp32)
__device__ float g_xc[ML * D_INNER];         // 8192 x 2048 (fp32, for scan)
__device__ float g_dbc[ML * DBC_N];          // 8192 x 96
__device__ float g_dbcp[2 * ML * DBC_N];     // split-K partials for dbc
__device__ float g_delta[ML * D_INNER];      // 8192 x 2048

// fp16 hi/lo operand buffers
__device__ __half g_xhi [ML * D_MODEL],      g_xlo [ML * D_MODEL];
__device__ __half g_winhi[2*D_INNER*D_MODEL];                 // 2-pass: hi only
__device__ __half g_wxhi[DBC_N * D_INNER],   g_wxlo[DBC_N * D_INNER];
__device__ __half g_wdthi[D_INNER*DT_RANK],  g_wdtlo[D_INNER*DT_RANK];
__device__ __half g_wouthi[D_MODEL*D_INNER];                  // 2-pass: hi only
__device__ __half g_xchi[ML * D_INNER],      g_xclo[ML * D_INNER];
__device__ __half g_dthi[ML * DT_RANK],      g_dtlo[ML * DT_RANK];
__device__ __half g_yhi [ML * D_INNER],      g_ylo [ML * D_INNER];

// ======================= low-level helpers (base sm_103 ISA only) ============
__device__ __forceinline__ uint32_t smem_to_u32(const void* p) {
    uint32_t a;
    asm("{ .reg .u64 t; cvta.to.shared.u64 t, %1; cvt.u32.u64 %0, t; }"
        : "=r"(a) : "l"(p));
    return a;
}
__device__ __forceinline__ void cp_async16(uint32_t dst, const void* src, bool pred) {
    int sz = pred ? 16 : 0;
    asm volatile("cp.async.cg.shared.global [%0], [%1], 16, %2;"
                 :: "r"(dst), "l"(src), "r"(sz) : "memory");
}
#define CP_COMMIT() asm volatile("cp.async.commit_group;" ::: "memory")
template <int N>
__device__ __forceinline__ void cp_wait() {
    asm volatile("cp.async.wait_group %0;" :: "n"(N) : "memory");
}
__device__ __forceinline__ void ldsm4(uint32_t* r, uint32_t addr) {
    asm volatile("ldmatrix.sync.aligned.m8n8.x4.shared.b16 {%0,%1,%2,%3}, [%4];"
                 : "=r"(r[0]), "=r"(r[1]), "=r"(r[2]), "=r"(r[3]) : "r"(addr));
}
__device__ __forceinline__ void mma16816(float* d, const uint32_t* a, const uint32_t* b) {
    asm volatile(
        "mma.sync.aligned.m16n8k16.row.col.f32.f16.f16.f32 "
        "{%0,%1,%2,%3}, {%4,%5,%6,%7}, {%8,%9}, {%0,%1,%2,%3};"
        : "+f"(d[0]), "+f"(d[1]), "+f"(d[2]), "+f"(d[3])
        : "r"(a[0]), "r"(a[1]), "r"(a[2]), "r"(a[3]), "r"(b[0]), "r"(b[1]));
}

// ======================= split-fp16 GEMM (mma.sync) ==========================
// C[M,N] = A[M,K] * B[N,K]^T, fp32 accumulate.
//   NPASS=3: hi*Hi + lo*Hi + hi*Lo   (A,B both 22-bit)
//   NPASS=2: hi*Hi + lo*Hi           (A 22-bit, B fp16)  -> no Bl tile at all
// CTA tile 128x128, BK=32, 8 warps (warp tile 32x64), 4-stage cp.async pipeline.
// smem rows padded to 40 fp16 (80B) -> conflict-free ldmatrix.
// Split-K: grid.x = ntiles_n * nsplit; partial C slabs csplit_stride apart.
// Modes: 0 plain fp32 C; 2 softplus(v + bias[col]).
#define TILE_BYTES  10240                  // 128 rows * 80B
#define NSTAGE 4
#define OFF_AH 0
#define OFF_AL TILE_BYTES
#define OFF_BH (2 * TILE_BYTES)
#define OFF_BL (3 * TILE_BYTES)

template <int NPASS>
__device__ __forceinline__ void load_stage(
    uint32_t sb, const __half* __restrict__ Ahi, const __half* __restrict__ Alo,
    const __half* __restrict__ Bhi, const __half* __restrict__ Blo,
    int lda, int ldb, int N, int m0, int n0, int kbase, int tid)
{
#pragma unroll
    for (int i = 0; i < 2; i++) {
        const int idx = i * 256 + tid;            // 0..511
        const int r = idx >> 2, seg = idx & 3;
        const size_t ga = (size_t)(m0 + r) * lda + kbase + seg * 8;
        const uint32_t da = sb + r * 80 + seg * 16;
        cp_async16(da + OFF_AH, Ahi + ga, true);
        cp_async16(da + OFF_AL, Alo + ga, true);
        const bool v = (n0 + r) < N;
        const size_t gb = (size_t)(n0 + (v ? r : 0)) * ldb + kbase + seg * 8;
        cp_async16(da + OFF_BH, Bhi + gb, v);
        if (NPASS == 3) cp_async16(da + OFF_BL, Blo + gb, v);
    }
}

template <int NPASS>
__global__ __launch_bounds__(256) void gemm_f16(
    const __half* __restrict__ Ahi, const __half* __restrict__ Alo,
    const __half* __restrict__ Bhi, const __half* __restrict__ Blo,
    int lda, int ldb, int Ksplit, int nsplit,
    int N, int ldc, size_t csplit_stride, float* __restrict__ C,
    int mode, const float* __restrict__ bias)
{
    constexpr int SB = (2 + NPASS) * TILE_BYTES;   // bytes per stage
    extern __shared__ char smem[];
    const uint32_t sbase = smem_to_u32(smem);
    const int tid  = threadIdx.x;
    const int wid  = tid >> 5;
    const int lane = tid & 31;
    const int ntile = blockIdx.x / nsplit;
    const int split = blockIdx.x % nsplit;
    const int m0 = blockIdx.y * 128;
    const int n0 = ntile * 128;
    const int k0 = split * Ksplit;
    Ahi += k0; Alo += k0; Bhi += k0; if (NPASS == 3) Blo += k0;
    C += (size_t)split * csplit_stride;
    const int wm = wid >> 1;          // 0..3
    const int wn = wid & 1;           // 0..1

    // ldmatrix lane addressing
    const int lr = lane & 7, lg = lane >> 3;       // lg 0..3
    const int a_row = ((lg & 1) << 3) + lr;        // 0..15
    const int a_col = (lg >> 1) << 3;              // 0 or 8 (elements)
    const int b_row = ((lg >> 1) << 3) + lr;       // 0..15
    const int b_col = (lg & 1) << 3;               // 0 or 8

    float acc[2][8][4];
#pragma unroll
    for (int mi = 0; mi < 2; mi++)
#pragma unroll
        for (int nj = 0; nj < 8; nj++)
#pragma unroll
            for (int e = 0; e < 4; e++) acc[mi][nj][e] = 0.f;

    const int KB = Ksplit >> 5;    // k-blocks of 32

    // prologue: issue up to NSTAGE-1 stages
#pragma unroll
    for (int s = 0; s < NSTAGE - 1; s++) {
        if (s < KB) {
            load_stage<NPASS>(sbase + s * SB, Ahi, Alo, Bhi, Blo,
                              lda, ldb, N, m0, n0, s << 5, tid);
            CP_COMMIT();
        }
    }

    for (int kb = 0; kb < KB; kb++) {
        const int rem = KB - 1 - kb;
        if (rem >= 2)      cp_wait<2>();
        else if (rem == 1) cp_wait<1>();
        else               cp_wait<0>();
        __syncthreads();

        const int ks2 = kb + NSTAGE - 1;
        if (ks2 < KB) {
            load_stage<NPASS>(sbase + (ks2 & (NSTAGE - 1)) * SB,
                              Ahi, Alo, Bhi, Blo, lda, ldb, N, m0, n0, ks2 << 5, tid);
            CP_COMMIT();
        }

        const uint32_t st = sbase + (kb & (NSTAGE - 1)) * SB;
#pragma unroll
        for (int ks = 0; ks < 2; ks++) {
            const uint32_t aoff = st + (wm * 32 + a_row) * 80 + (ks * 16 + a_col) * 2;
            const uint32_t boff = st + OFF_BH + (wn * 64 + b_row) * 80 + (ks * 16 + b_col) * 2;
            uint32_t ah[2][4], al[2][4], bh[4][4];
            ldsm4(ah[0], aoff + OFF_AH);
            ldsm4(ah[1], aoff + OFF_AH + 16 * 80);
            ldsm4(bh[0], boff);
            ldsm4(bh[1], boff + 16 * 80);
            ldsm4(bh[2], boff + 32 * 80);
            ldsm4(bh[3], boff + 48 * 80);
#pragma unroll
            for (int mi = 0; mi < 2; mi++)
#pragma unroll
                for (int nj = 0; nj < 8; nj++)
                    mma16816(acc[mi][nj], ah[mi], &bh[nj >> 1][(nj & 1) * 2]);
            ldsm4(al[0], aoff + OFF_AL);
            ldsm4(al[1], aoff + OFF_AL + 16 * 80);
#pragma unroll
            for (int mi = 0; mi < 2; mi++)
#pragma unroll
                for (int nj = 0; nj < 8; nj++)
                    mma16816(acc[mi][nj], al[mi], &bh[nj >> 1][(nj & 1) * 2]);
            if (NPASS == 3) {
                uint32_t bl[4][4];
                ldsm4(bl[0], boff + TILE_BYTES);
                ldsm4(bl[1], boff + TILE_BYTES + 16 * 80);
                ldsm4(bl[2], boff + TILE_BYTES + 32 * 80);
                ldsm4(bl[3], boff + TILE_BYTES + 48 * 80);
#pragma unroll
                for (int mi = 0; mi < 2; mi++)
#pragma unroll
                    for (int nj = 0; nj < 8; nj++)
                        mma16816(acc[mi][nj], ah[mi], &bl[nj >> 1][(nj & 1) * 2]);
            }
        }
        __syncthreads();
    }

    // ----- epilogue -----
    const int rbase = m0 + wm * 32 + (lane >> 2);
    const int cbase = n0 + wn * 64 + (lane & 3) * 2;
#pragma unroll
    for (int mi = 0; mi < 2; mi++) {
#pragma unroll
        for (int e = 0; e < 2; e++) {
            const int row = rbase + mi * 16 + e * 8;
#pragma unroll
            for (int nj = 0; nj < 8; nj++) {
                const int c = cbase + nj * 8;
                if (c >= N) continue;
                float v0 = acc[mi][nj][e * 2 + 0];
                float v1 = acc[mi][nj][e * 2 + 1];
                if (mode == 2) {
                    float t0 = v0 + bias[c];
                    float t1 = v1 + bias[c + 1];
                    v0 = (t0 > 20.f) ? t0 : log1pf(__expf(t0));
                    v1 = (t1 > 20.f) ? t1 : log1pf(__expf(t1));
                }
                *(float2*)(C + (size_t)row * ldc + c) = make_float2(v0, v1);
            }
        }
    }
}

// ---------------- fp32 -> fp16 hi/lo conversions ----------------
__global__ __launch_bounds__(256) void cvt_hilo_h(
    const float* __restrict__ src, __half* __restrict__ hi,
    __half* __restrict__ lo, int n)
{
    for (int i = blockIdx.x * 256 + threadIdx.x; i < n; i += gridDim.x * 256) {
        const float v = src[i];
        const __half h = __float2half_rn(v);
        hi[i] = h;
        lo[i] = __float2half_rn(v - __half2float(h));
    }
}
__global__ __launch_bounds__(256) void cvt_hi_h(
    const float* __restrict__ src, __half* __restrict__ hi, int n)
{
    for (int i = blockIdx.x * 256 + threadIdx.x; i < n; i += gridDim.x * 256)
        hi[i] = __float2half_rn(src[i]);
}

// ---------------- split-K reduce for dbc + dt hi/lo emission -----------------
__global__ __launch_bounds__(256) void reduce_dbc_kernel()
{
    const int n = ML * DBC_N;
    for (int i = blockIdx.x * 256 + threadIdx.x; i < n; i += gridDim.x * 256) {
        const float s = g_dbcp[i] + g_dbcp[i + ML * DBC_N];
        g_dbc[i] = s;
        const int col = i % DBC_N;
        if (col < DT_RANK) {
            const int row = i / DBC_N;
            const __half h = __float2half_rn(s);
            g_dthi[row * DT_RANK + col] = h;
            g_dtlo[row * DT_RANK + col] = __float2half_rn(s - __half2float(h));
        }
    }
}

// ---------------- causal depthwise conv (k=4) + bias + SiLU ----------------
__global__ __launch_bounds__(256) void conv_silu_kernel(
    const float* __restrict__ conv_w, const float* __restrict__ conv_b)
{
    const int d  = blockIdx.x * 256 + threadIdx.x;
    const int l0 = blockIdx.y * 128;
    const int b  = blockIdx.z;

    const float w0 = conv_w[d * 4 + 0], w1 = conv_w[d * 4 + 1];
    const float w2 = conv_w[d * 4 + 2], w3 = conv_w[d * 4 + 3];
    const float bias = conv_b[d];

    const float* in = g_xz + (size_t)(b * LENGTH) * (2 * D_INNER) + d;
    float x0 = 0.f, x1 = 0.f, x2 = 0.f;
    if (l0 >= 3) {
        x0 = in[(size_t)(l0 - 3) * (2 * D_INNER)];
        x1 = in[(size_t)(l0 - 2) * (2 * D_INNER)];
        x2 = in[(size_t)(l0 - 1) * (2 * D_INNER)];
    }
    size_t o = (size_t)(b * LENGTH + l0) * D_INNER + d;
#pragma unroll 4
    for (int l = l0; l < l0 + 128; l++) {
        const float x3 = in[(size_t)l * (2 * D_INNER)];
        float v = fmaf(w0, x0, fmaf(w1, x1, fmaf(w2, x2, fmaf(w3, x3, bias))));
        v = v / (1.f + __expf(-v));
        g_xc[o] = v;
        const __half h = __float2half_rn(v);
        g_xchi[o] = h;
        g_xclo[o] = __float2half_rn(v - __half2float(h));
        o += D_INNER;
        x0 = x1; x1 = x2; x2 = x3;
    }
}

// ---------------- selective scan + D*x + silu(z) gating (pipelined) ----------
#define SCAN_CH 4
__global__ __launch_bounds__(32) void scan_kernel(
    const float* __restrict__ A_raw, const float* __restrict__ Dvec)
{
    const int lane = threadIdx.x & 31;
    const int d  = blockIdx.x * 8 + (lane & 7);
    const int n0 = (lane >> 3) * 4;
    const int b  = blockIdx.y;

    const float A0 = -expf(A_raw[(n0 + 0) * D_INNER + d]);
    const float A1 = -expf(A_raw[(n0 + 1) * D_INNER + d]);
    const float A2 = -expf(A_raw[(n0 + 2) * D_INNER + d]);
    const float A3 = -expf(A_raw[(n0 + 3) * D_INNER + d]);
    const float Dv = Dvec[d];

    const int row0 = b * LENGTH;
    const float* dp = g_delta + (size_t)row0 * D_INNER + d;
    const float* xp = g_xc    + (size_t)row0 * D_INNER + d;
    const float* zp = g_xz    + (size_t)row0 * (2 * D_INNER) + D_INNER + d;
    const float4* Bp = (const float4*)(g_dbc + (size_t)row0 * DBC_N + DT_RANK + n0);
    const float4* Cp = (const float4*)(g_dbc + (size_t)row0 * DBC_N + DT_RANK + D_STATE + n0);
    const size_t yo0 = (size_t)row0 * D_INNER + d;

    float  dlt[2][SCAN_CH], xv[2][SCAN_CH], zv[2][SCAN_CH];
    float4 Bv[2][SCAN_CH], Cv[2][SCAN_CH];

#pragma unroll
    for (int i = 0; i < SCAN_CH; i++) {
        dlt[0][i] = dp[(size_t)i * D_INNER];
        xv [0][i] = xp[(size_t)i * D_INNER];
        zv [0][i] = zp[(size_t)i * 2 * D_INNER];
        Bv [0][i] = Bp[i * (DBC_N / 4)];
        Cv [0][i] = Cp[i * (DBC_N / 4)];
    }

    float h0 = 0.f, h1 = 0.f, h2 = 0.f, h3 = 0.f;

    const int NCH = LENGTH / SCAN_CH;   // 512
#pragma unroll 2
    for (int c = 0; c < NCH; c++) {
        const int cur = c & 1, nxt = cur ^ 1;
        if (c + 1 < NCH) {
            const size_t lb = (size_t)(c + 1) * SCAN_CH;
#pragma unroll
            for (int i = 0; i < SCAN_CH; i++) {
                dlt[nxt][i] = dp[(lb + i) * D_INNER];
                xv [nxt][i] = xp[(lb + i) * D_INNER];
                zv [nxt][i] = zp[(lb + i) * 2 * D_INNER];
                Bv [nxt][i] = Bp[(lb + i) * (DBC_N / 4)];
                Cv [nxt][i] = Cp[(lb + i) * (DBC_N / 4)];
            }
        }
#pragma unroll
        for (int i = 0; i < SCAN_CH; i++) {
            const float dl = dlt[cur][i];
            const float xx = xv[cur][i];
            const float dx = dl * xx;
            const float4 B4 = Bv[cur][i];
            const float4 C4 = Cv[cur][i];
            h0 = fmaf(__expf(dl * A0), h0, B4.x * dx);
            h1 = fmaf(__expf(dl * A1), h1, B4.y * dx);
            h2 = fmaf(__expf(dl * A2), h2, B4.z * dx);
            h3 = fmaf(__expf(dl * A3), h3, B4.w * dx);
            float p = C4.x * h0 + C4.y * h1 + C4.z * h2 + C4.w * h3;
            p += __shfl_xor_sync(0xffffffffu, p, 8);
            p += __shfl_xor_sync(0xffffffffu, p, 16);
            if (n0 == 0) {
                const float zz = zv[cur][i];
                const float sz = zz / (1.f + __expf(-zz));
                const float yv = (p + Dv * xx) * sz;
                const __half hb = __float2half_rn(yv);
                const size_t yo = yo0 + (size_t)(c * SCAN_CH + i) * D_INNER;
                g_yhi[yo] = hb;
                g_ylo[yo] = __float2half_rn(yv - __half2float(hb));
            }
        }
    }
}

// ---------------- host launch ----------------
extern "C" void kernel_launch(void* const* d_in, const int* in_sizes, int n_in,
                              void* d_out, int out_size)
{
    const float* x      = (const float*)d_in[0];
    const float* W_in   = (const float*)d_in[1];
    const float* conv_w = (const float*)d_in[2];
    const float* conv_b = (const float*)d_in[3];
    const float* W_x    = (const float*)d_in[4];
    const float* W_dt   = (const float*)d_in[5];
    const float* b_dt   = (const float*)d_in[6];
    const float* A_raw  = (const float*)d_in[7];
    const float* Dvec   = (const float*)d_in[8];
    const float* W_out  = (const float*)d_in[9];
    float* out = (float*)d_out;

    float *p_xz, *p_dbcp;
    float *p_delta;
    __half *p_xhi, *p_xlo, *p_winhi, *p_wxhi, *p_wxlo;
    __half *p_wdthi, *p_wdtlo, *p_wouthi;
    __half *p_xchi, *p_xclo, *p_dthi, *p_dtlo, *p_yhi, *p_ylo;
    cudaGetSymbolAddress((void**)&p_xz,    g_xz);
    cudaGetSymbolAddress((void**)&p_dbcp,  g_dbcp);
    cudaGetSymbolAddress((void**)&p_delta, g_delta);
    cudaGetSymbolAddress((void**)&p_xhi,   g_xhi);
    cudaGetSymbolAddress((void**)&p_xlo,   g_xlo);
    cudaGetSymbolAddress((void**)&p_winhi, g_winhi);
    cudaGetSymbolAddress((void**)&p_wxhi,  g_wxhi);
    cudaGetSymbolAddress((void**)&p_wxlo,  g_wxlo);
    cudaGetSymbolAddress((void**)&p_wdthi, g_wdthi);
    cudaGetSymbolAddress((void**)&p_wdtlo, g_wdtlo);
    cudaGetSymbolAddress((void**)&p_wouthi,g_wouthi);
    cudaGetSymbolAddress((void**)&p_xchi,  g_xchi);
    cudaGetSymbolAddress((void**)&p_xclo,  g_xclo);
    cudaGetSymbolAddress((void**)&p_dthi,  g_dthi);
    cudaGetSymbolAddress((void**)&p_dtlo,  g_dtlo);
    cudaGetSymbolAddress((void**)&p_yhi,   g_yhi);
    cudaGetSymbolAddress((void**)&p_ylo,   g_ylo);

    const int SMEM2 = NSTAGE * 4 * TILE_BYTES;  // NPASS=2: 4 tiles? no: (2+2)=4 tiles
    const int SMEM3 = NSTAGE * 5 * TILE_BYTES;  // NPASS=3: 5 tiles
    cudaFuncSetAttribute(gemm_f16<2>, cudaFuncAttributeMaxDynamicSharedMemorySize, SMEM2);
    cudaFuncSetAttribute(gemm_f16<3>, cudaFuncAttributeMaxDynamicSharedMemorySize, SMEM3);

    // 0) conversions
    cvt_hilo_h<<<1024, 256>>>(x,     p_xhi,   p_xlo,  ML * D_MODEL);
    cvt_hi_h  <<<1024, 256>>>(W_in,  p_winhi,         2 * D_INNER * D_MODEL);
    cvt_hilo_h<<<256,  256>>>(W_x,   p_wxhi,  p_wxlo, DBC_N * D_INNER);
    cvt_hilo_h<<<256,  256>>>(W_dt,  p_wdthi, p_wdtlo,D_INNER * DT_RANK);
    cvt_hi_h  <<<1024, 256>>>(W_out, p_wouthi,        D_MODEL * D_INNER);

    // 1) xz = x @ W_in^T : 2-pass fp16 (A 22-bit, B fp16)
    {
        dim3 grid((2 * D_INNER) / 128, ML / 128);
        gemm_f16<2><<<grid, 256, SMEM2>>>(p_xhi, p_xlo, p_winhi, nullptr,
            D_MODEL, D_MODEL, D_MODEL, 1,
            2 * D_INNER, 2 * D_INNER, 0, p_xz, 0, nullptr);
    }
    // 2) causal conv + SiLU -> xc (fp32 + fp16 hi/lo)
    {
        dim3 grid(D_INNER / 256, LENGTH / 128, BATCH);
        conv_silu_kernel<<<grid, 256>>>(conv_w, conv_b);
    }
    // 3) dbc = xc @ W_x^T : 3-pass fp16, split-K=2 (128 CTAs), partials
    {
        dim3 grid(2, ML / 128);   // ntiles_n(1) * nsplit(2)
        gemm_f16<3><<<grid, 256, SMEM3>>>(p_xchi, p_xclo, p_wxhi, p_wxlo,
            D_INNER, D_INNER, D_INNER / 2, 2,
            DBC_N, DBC_N, (size_t)ML * DBC_N, p_dbcp, 0, nullptr);
        reduce_dbc_kernel<<<1024, 256>>>();
    }
    // 4) delta = softplus(dt @ W_dt^T + b_dt) : 3-pass fp16
    {
        dim3 grid(D_INNER / 128, ML / 128);
        gemm_f16<3><<<grid, 256, SMEM3>>>(p_dthi, p_dtlo, p_wdthi, p_wdtlo,
            DT_RANK, DT_RANK, DT_RANK, 1,
            D_INNER, D_INNER, 0, p_delta, 2, b_dt);
    }
    // 5) selective scan -> y (fp16 hi/lo), pipelined
    {
        dim3 grid(D_INNER / 8, BATCH);
        scan_kernel<<<grid, 32>>>(A_raw, Dvec);
    }
    // 6) out = y @ W_out^T : 2-pass fp16
    {
        dim3 grid(D_MODEL / 128, ML / 128);
        gemm_f16<2><<<grid, 256, SMEM2>>>(p_yhi, p_ylo, p_wouthi, nullptr,
            D_INNER, D_INNER, D_INNER, 1,
            D_MODEL, D_MODEL, 0, out, 0, nullptr);
    }
}

// round 13
// speedup vs baseline: 1.6799x; 1.3567x over previous
#include <cuda_runtime.h>
#include <cuda_fp16.h>
#include <math.h>
#include <stdint.h>

// Problem constants
#define D_MODEL 1024
#define D_STATE 16
#define D_CONV  4
#define D_INNER 2048
#define DT_RANK 64
#define BATCH   4
#define LENGTH  2048
#define ML      (BATCH * LENGTH)          // 8192 rows
#define DBC_N   (DT_RANK + 2 * D_STATE)   // 96

// ---------------- scratch (static __device__, no allocations) ----------------
__device__ float g_xz[ML * 2 * D_INNER];     // 8192 x 4096 (fp32)
__device__ float g_xc[ML * D_INNER];         // 8192 x 2048 (fp32, for scan)
__device__ float g_dbc[ML * DBC_N];          // 8192 x 96
__device__ float g_dbcp[2 * ML * DBC_N];     // split-K partials for dbc
__device__ float g_delta[ML * D_INNER];      // 8192 x 2048

// fp16 hi/lo operand buffers
__device__ __half g_xhi [ML * D_MODEL],      g_xlo [ML * D_MODEL];
__device__ __half g_winhi[2*D_INNER*D_MODEL];                 // hi only
__device__ __half g_wxhi[DBC_N * D_INNER];                    // hi only
__device__ __half g_wdthi[D_INNER*DT_RANK];                   // hi only
__device__ __half g_wouthi[D_MODEL*D_INNER];                  // hi only
__device__ __half g_xchi[ML * D_INNER],      g_xclo[ML * D_INNER];
__device__ __half g_dthi[ML * DT_RANK],      g_dtlo[ML * DT_RANK];
__device__ __half g_yhi [ML * D_INNER];

// ======================= low-level helpers (base sm_103 ISA only) ============
__device__ __forceinline__ uint32_t smem_to_u32(const void* p) {
    uint32_t a;
    asm("{ .reg .u64 t; cvta.to.shared.u64 t, %1; cvt.u32.u64 %0, t; }"
        : "=r"(a) : "l"(p));
    return a;
}
__device__ __forceinline__ void cp_async16(uint32_t dst, const void* src, bool pred) {
    int sz = pred ? 16 : 0;
    asm volatile("cp.async.cg.shared.global [%0], [%1], 16, %2;"
                 :: "r"(dst), "l"(src), "r"(sz) : "memory");
}
#define CP_COMMIT() asm volatile("cp.async.commit_group;" ::: "memory")
template <int N>
__device__ __forceinline__ void cp_wait() {
    asm volatile("cp.async.wait_group %0;" :: "n"(N) : "memory");
}
__device__ __forceinline__ void ldsm4(uint32_t* r, uint32_t addr) {
    asm volatile("ldmatrix.sync.aligned.m8n8.x4.shared.b16 {%0,%1,%2,%3}, [%4];"
                 : "=r"(r[0]), "=r"(r[1]), "=r"(r[2]), "=r"(r[3]) : "r"(addr));
}
__device__ __forceinline__ void mma16816(float* d, const uint32_t* a, const uint32_t* b) {
    asm volatile(
        "mma.sync.aligned.m16n8k16.row.col.f32.f16.f16.f32 "
        "{%0,%1,%2,%3}, {%4,%5,%6,%7}, {%8,%9}, {%0,%1,%2,%3};"
        : "+f"(d[0]), "+f"(d[1]), "+f"(d[2]), "+f"(d[3])
        : "r"(a[0]), "r"(a[1]), "r"(a[2]), "r"(a[3]), "r"(b[0]), "r"(b[1]));
}

// ======================= split-fp16 GEMM (mma.sync) ==========================
// C[M,N] = A[M,K] * B[N,K]^T, fp32 accumulate.
//   NPASS=1: hi*Hi                   (A fp16, B fp16)
//   NPASS=2: hi*Hi + lo*Hi           (A 22-bit, B fp16)
//   NPASS=3: hi*Hi + lo*Hi + hi*Lo   (A,B both 22-bit)
// CTA tile 128x128, BK=32, 8 warps (warp tile 32x64), 4-stage cp.async pipeline,
// single __syncthreads per k-block (compute-then-load ordering).
// smem rows padded to 40 fp16 (80B) -> conflict-free ldmatrix.
// Split-K: grid.x = ntiles_n * nsplit; partial C slabs csplit_stride apart.
// Modes: 0 plain fp32 C; 2 softplus(v + bias[col]).
#define TILE_BYTES  10240                  // 128 rows * 80B
#define NSTAGE 4

template <int NPASS>
__device__ __forceinline__ void load_stage(
    uint32_t sb, const __half* __restrict__ Ahi, const __half* __restrict__ Alo,
    const __half* __restrict__ Bhi, const __half* __restrict__ Blo,
    int lda, int ldb, int N, int m0, int n0, int kbase, int tid)
{
    constexpr int OFF_AL = TILE_BYTES;
    constexpr int OFF_BH = (NPASS >= 2 ? 2 : 1) * TILE_BYTES;
    constexpr int OFF_BL = 3 * TILE_BYTES;
#pragma unroll
    for (int i = 0; i < 2; i++) {
        const int idx = i * 256 + tid;            // 0..511
        const int r = idx >> 2, seg = idx & 3;
        const size_t ga = (size_t)(m0 + r) * lda + kbase + seg * 8;
        const uint32_t da = sb + r * 80 + seg * 16;
        cp_async16(da, Ahi + ga, true);
        if (NPASS >= 2) cp_async16(da + OFF_AL, Alo + ga, true);
        const bool v = (n0 + r) < N;
        const size_t gb = (size_t)(n0 + (v ? r : 0)) * ldb + kbase + seg * 8;
        cp_async16(da + OFF_BH, Bhi + gb, v);
        if (NPASS == 3) cp_async16(da + OFF_BL, Blo + gb, v);
    }
}

template <int NPASS>
__global__ __launch_bounds__(256) void gemm_f16(
    const __half* __restrict__ Ahi, const __half* __restrict__ Alo,
    const __half* __restrict__ Bhi, const __half* __restrict__ Blo,
    int lda, int ldb, int Ksplit, int nsplit,
    int N, int ldc, size_t csplit_stride, float* __restrict__ C,
    int mode, const float* __restrict__ bias)
{
    constexpr int NT = (NPASS == 1) ? 2 : (NPASS == 2 ? 3 : 4);
    constexpr int SB = NT * TILE_BYTES;            // bytes per stage
    constexpr int OFF_AL = TILE_BYTES;
    constexpr int OFF_BH = (NPASS >= 2 ? 2 : 1) * TILE_BYTES;
    constexpr int OFF_BL = 3 * TILE_BYTES;
    extern __shared__ char smem[];
    const uint32_t sbase = smem_to_u32(smem);
    const int tid  = threadIdx.x;
    const int wid  = tid >> 5;
    const int lane = tid & 31;
    const int ntile = blockIdx.x / nsplit;
    const int split = blockIdx.x % nsplit;
    const int m0 = blockIdx.y * 128;
    const int n0 = ntile * 128;
    const int k0 = split * Ksplit;
    Ahi += k0; if (NPASS >= 2) Alo += k0;
    Bhi += k0; if (NPASS == 3) Blo += k0;
    C += (size_t)split * csplit_stride;
    const int wm = wid >> 1;          // 0..3
    const int wn = wid & 1;           // 0..1

    // ldmatrix lane addressing
    const int lr = lane & 7, lg = lane >> 3;       // lg 0..3
    const int a_row = ((lg & 1) << 3) + lr;        // 0..15
    const int a_col = (lg >> 1) << 3;              // 0 or 8 (elements)
    const int b_row = ((lg >> 1) << 3) + lr;       // 0..15
    const int b_col = (lg & 1) << 3;               // 0 or 8

    float acc[2][8][4];
#pragma unroll
    for (int mi = 0; mi < 2; mi++)
#pragma unroll
        for (int nj = 0; nj < 8; nj++)
#pragma unroll
            for (int e = 0; e < 4; e++) acc[mi][nj][e] = 0.f;

    const int KB = Ksplit >> 5;    // k-blocks of 32

    // prologue: issue up to NSTAGE-1 stages
#pragma unroll
    for (int s = 0; s < NSTAGE - 1; s++) {
        if (s < KB) {
            load_stage<NPASS>(sbase + s * SB, Ahi, Alo, Bhi, Blo,
                              lda, ldb, N, m0, n0, s << 5, tid);
            CP_COMMIT();
        }
    }

    for (int kb = 0; kb < KB; kb++) {
        const int rem = KB - 1 - kb;
        if (rem >= 2)      cp_wait<2>();
        else if (rem == 1) cp_wait<1>();
        else               cp_wait<0>();
        __syncthreads();

        const uint32_t st = sbase + (kb & (NSTAGE - 1)) * SB;
#pragma unroll
        for (int ks = 0; ks < 2; ks++) {
            const uint32_t aoff = st + (wm * 32 + a_row) * 80 + (ks * 16 + a_col) * 2;
            const uint32_t boff = st + OFF_BH + (wn * 64 + b_row) * 80 + (ks * 16 + b_col) * 2;
            uint32_t ah[2][4], bh[4][4];
            ldsm4(ah[0], aoff);
            ldsm4(ah[1], aoff + 16 * 80);
            ldsm4(bh[0], boff);
            ldsm4(bh[1], boff + 16 * 80);
            ldsm4(bh[2], boff + 32 * 80);
            ldsm4(bh[3], boff + 48 * 80);
#pragma unroll
            for (int mi = 0; mi < 2; mi++)
#pragma unroll
                for (int nj = 0; nj < 8; nj++)
                    mma16816(acc[mi][nj], ah[mi], &bh[nj >> 1][(nj & 1) * 2]);
            if (NPASS >= 2) {
                uint32_t al[2][4];
                ldsm4(al[0], aoff + OFF_AL);
                ldsm4(al[1], aoff + OFF_AL + 16 * 80);
#pragma unroll
                for (int mi = 0; mi < 2; mi++)
#pragma unroll
                    for (int nj = 0; nj < 8; nj++)
                        mma16816(acc[mi][nj], al[mi], &bh[nj >> 1][(nj & 1) * 2]);
            }
            if (NPASS == 3) {
                uint32_t bl[4][4];
                ldsm4(bl[0], boff + (OFF_BL - OFF_BH));
                ldsm4(bl[1], boff + (OFF_BL - OFF_BH) + 16 * 80);
                ldsm4(bl[2], boff + (OFF_BL - OFF_BH) + 32 * 80);
                ldsm4(bl[3], boff + (OFF_BL - OFF_BH) + 48 * 80);
#pragma unroll
                for (int mi = 0; mi < 2; mi++)
#pragma unroll
                    for (int nj = 0; nj < 8; nj++)
                        mma16816(acc[mi][nj], ah[mi], &bl[nj >> 1][(nj & 1) * 2]);
            }
        }

        // issue stage kb+NSTAGE-1 (its buffer (kb-1)&3 is free: all warps passed
        // this iteration's barrier, hence finished compute(kb-1))
        const int ks2 = kb + NSTAGE - 1;
        if (ks2 < KB) {
            load_stage<NPASS>(sbase + (ks2 & (NSTAGE - 1)) * SB,
                              Ahi, Alo, Bhi, Blo, lda, ldb, N, m0, n0, ks2 << 5, tid);
            CP_COMMIT();
        }
    }

    // ----- epilogue -----
    const int rbase = m0 + wm * 32 + (lane >> 2);
    const int cbase = n0 + wn * 64 + (lane & 3) * 2;
#pragma unroll
    for (int mi = 0; mi < 2; mi++) {
#pragma unroll
        for (int e = 0; e < 2; e++) {
            const int row = rbase + mi * 16 + e * 8;
#pragma unroll
            for (int nj = 0; nj < 8; nj++) {
                const int c = cbase + nj * 8;
                if (c >= N) continue;
                float v0 = acc[mi][nj][e * 2 + 0];
                float v1 = acc[mi][nj][e * 2 + 1];
                if (mode == 2) {
                    float t0 = v0 + bias[c];
                    float t1 = v1 + bias[c + 1];
                    v0 = (t0 > 20.f) ? t0 : log1pf(__expf(t0));
                    v1 = (t1 > 20.f) ? t1 : log1pf(__expf(t1));
                }
                *(float2*)(C + (size_t)row * ldc + c) = make_float2(v0, v1);
            }
        }
    }
}

// ---------------- fp32 -> fp16 hi/lo conversions ----------------
__global__ __launch_bounds__(256) void cvt_hilo_h(
    const float* __restrict__ src, __half* __restrict__ hi,
    __half* __restrict__ lo, int n)
{
    for (int i = blockIdx.x * 256 + threadIdx.x; i < n; i += gridDim.x * 256) {
        const float v = src[i];
        const __half h = __float2half_rn(v);
        hi[i] = h;
        lo[i] = __float2half_rn(v - __half2float(h));
    }
}
__global__ __launch_bounds__(256) void cvt_hi_h(
    const float* __restrict__ src, __half* __restrict__ hi, int n)
{
    for (int i = blockIdx.x * 256 + threadIdx.x; i < n; i += gridDim.x * 256)
        hi[i] = __float2half_rn(src[i]);
}

// ---------------- split-K reduce for dbc + dt hi/lo emission -----------------
__global__ __launch_bounds__(256) void reduce_dbc_kernel()
{
    const int n = ML * DBC_N;
    for (int i = blockIdx.x * 256 + threadIdx.x; i < n; i += gridDim.x * 256) {
        const float s = g_dbcp[i] + g_dbcp[i + ML * DBC_N];
        g_dbc[i] = s;
        const int col = i % DBC_N;
        if (col < DT_RANK) {
            const int row = i / DBC_N;
            const __half h = __float2half_rn(s);
            g_dthi[row * DT_RANK + col] = h;
            g_dtlo[row * DT_RANK + col] = __float2half_rn(s - __half2float(h));
        }
    }
}

// ---------------- causal depthwise conv (k=4) + bias + SiLU ----------------
__global__ __launch_bounds__(256) void conv_silu_kernel(
    const float* __restrict__ conv_w, const float* __restrict__ conv_b)
{
    const int d  = blockIdx.x * 256 + threadIdx.x;
    const int l0 = blockIdx.y * 128;
    const int b  = blockIdx.z;

    const float w0 = conv_w[d * 4 + 0], w1 = conv_w[d * 4 + 1];
    const float w2 = conv_w[d * 4 + 2], w3 = conv_w[d * 4 + 3];
    const float bias = conv_b[d];

    const float* in = g_xz + (size_t)(b * LENGTH) * (2 * D_INNER) + d;
    float x0 = 0.f, x1 = 0.f, x2 = 0.f;
    if (l0 >= 3) {
        x0 = in[(size_t)(l0 - 3) * (2 * D_INNER)];
        x1 = in[(size_t)(l0 - 2) * (2 * D_INNER)];
        x2 = in[(size_t)(l0 - 1) * (2 * D_INNER)];
    }
    size_t o = (size_t)(b * LENGTH + l0) * D_INNER + d;
#pragma unroll 4
    for (int l = l0; l < l0 + 128; l++) {
        const float x3 = in[(size_t)l * (2 * D_INNER)];
        float v = fmaf(w0, x0, fmaf(w1, x1, fmaf(w2, x2, fmaf(w3, x3, bias))));
        v = v / (1.f + __expf(-v));
        g_xc[o] = v;
        const __half h = __float2half_rn(v);
        g_xchi[o] = h;
        g_xclo[o] = __float2half_rn(v - __half2float(h));
        o += D_INNER;
        x0 = x1; x1 = x2; x2 = x3;
    }
}

// ---------------- selective scan + D*x + silu(z) gating (pipelined) ----------
#define SCAN_CH 4
__global__ __launch_bounds__(32) void scan_kernel(
    const float* __restrict__ A_raw, const float* __restrict__ Dvec)
{
    const int lane = threadIdx.x & 31;
    const int d  = blockIdx.x * 8 + (lane & 7);
    const int n0 = (lane >> 3) * 4;
    const int b  = blockIdx.y;

    const float A0 = -expf(A_raw[(n0 + 0) * D_INNER + d]);
    const float A1 = -expf(A_raw[(n0 + 1) * D_INNER + d]);
    const float A2 = -expf(A_raw[(n0 + 2) * D_INNER + d]);
    const float A3 = -expf(A_raw[(n0 + 3) * D_INNER + d]);
    const float Dv = Dvec[d];

    const int row0 = b * LENGTH;
    const float* dp = g_delta + (size_t)row0 * D_INNER + d;
    const float* xp = g_xc    + (size_t)row0 * D_INNER + d;
    const float* zp = g_xz    + (size_t)row0 * (2 * D_INNER) + D_INNER + d;
    const float4* Bp = (const float4*)(g_dbc + (size_t)row0 * DBC_N + DT_RANK + n0);
    const float4* Cp = (const float4*)(g_dbc + (size_t)row0 * DBC_N + DT_RANK + D_STATE + n0);
    const size_t yo0 = (size_t)row0 * D_INNER + d;

    float  dlt[2][SCAN_CH], xv[2][SCAN_CH], zv[2][SCAN_CH];
    float4 Bv[2][SCAN_CH], Cv[2][SCAN_CH];

#pragma unroll
    for (int i = 0; i < SCAN_CH; i++) {
        dlt[0][i] = dp[(size_t)i * D_INNER];
        xv [0][i] = xp[(size_t)i * D_INNER];
        zv [0][i] = zp[(size_t)i * 2 * D_INNER];
        Bv [0][i] = Bp[i * (DBC_N / 4)];
        Cv [0][i] = Cp[i * (DBC_N / 4)];
    }

    float h0 = 0.f, h1 = 0.f, h2 = 0.f, h3 = 0.f;

    const int NCH = LENGTH / SCAN_CH;   // 512
#pragma unroll 2
    for (int c = 0; c < NCH; c++) {
        const int cur = c & 1, nxt = cur ^ 1;
        if (c + 1 < NCH) {
            const size_t lb = (size_t)(c + 1) * SCAN_CH;
#pragma unroll
            for (int i = 0; i < SCAN_CH; i++) {
                dlt[nxt][i] = dp[(lb + i) * D_INNER];
                xv [nxt][i] = xp[(lb + i) * D_INNER];
                zv [nxt][i] = zp[(lb + i) * 2 * D_INNER];
                Bv [nxt][i] = Bp[(lb + i) * (DBC_N / 4)];
                Cv [nxt][i] = Cp[(lb + i) * (DBC_N / 4)];
            }
        }
#pragma unroll
        for (int i = 0; i < SCAN_CH; i++) {
            const float dl = dlt[cur][i];
            const float xx = xv[cur][i];
            const float dx = dl * xx;
            const float4 B4 = Bv[cur][i];
            const float4 C4 = Cv[cur][i];
            h0 = fmaf(__expf(dl * A0), h0, B4.x * dx);
            h1 = fmaf(__expf(dl * A1), h1, B4.y * dx);
            h2 = fmaf(__expf(dl * A2), h2, B4.z * dx);
            h3 = fmaf(__expf(dl * A3), h3, B4.w * dx);
            float p = C4.x * h0 + C4.y * h1 + C4.z * h2 + C4.w * h3;
            p += __shfl_xor_sync(0xffffffffu, p, 8);
            p += __shfl_xor_sync(0xffffffffu, p, 16);
            if (n0 == 0) {
                const float zz = zv[cur][i];
                const float sz = zz / (1.f + __expf(-zz));
                const float yv = (p + Dv * xx) * sz;
                const size_t yo = yo0 + (size_t)(c * SCAN_CH + i) * D_INNER;
                g_yhi[yo] = __float2half_rn(yv);
            }
        }
    }
}

// ---------------- host launch ----------------
extern "C" void kernel_launch(void* const* d_in, const int* in_sizes, int n_in,
                              void* d_out, int out_size)
{
    const float* x      = (const float*)d_in[0];
    const float* W_in   = (const float*)d_in[1];
    const float* conv_w = (const float*)d_in[2];
    const float* conv_b = (const float*)d_in[3];
    const float* W_x    = (const float*)d_in[4];
    const float* W_dt   = (const float*)d_in[5];
    const float* b_dt   = (const float*)d_in[6];
    const float* A_raw  = (const float*)d_in[7];
    const float* Dvec   = (const float*)d_in[8];
    const float* W_out  = (const float*)d_in[9];
    float* out = (float*)d_out;

    float *p_xz, *p_dbcp, *p_delta;
    __half *p_xhi, *p_xlo, *p_winhi, *p_wxhi;
    __half *p_wdthi, *p_wouthi;
    __half *p_xchi, *p_xclo, *p_dthi, *p_dtlo, *p_yhi;
    cudaGetSymbolAddress((void**)&p_xz,    g_xz);
    cudaGetSymbolAddress((void**)&p_dbcp,  g_dbcp);
    cudaGetSymbolAddress((void**)&p_delta, g_delta);
    cudaGetSymbolAddress((void**)&p_xhi,   g_xhi);
    cudaGetSymbolAddress((void**)&p_xlo,   g_xlo);
    cudaGetSymbolAddress((void**)&p_winhi, g_winhi);
    cudaGetSymbolAddress((void**)&p_wxhi,  g_wxhi);
    cudaGetSymbolAddress((void**)&p_wdthi, g_wdthi);
    cudaGetSymbolAddress((void**)&p_wouthi,g_wouthi);
    cudaGetSymbolAddress((void**)&p_xchi,  g_xchi);
    cudaGetSymbolAddress((void**)&p_xclo,  g_xclo);
    cudaGetSymbolAddress((void**)&p_dthi,  g_dthi);
    cudaGetSymbolAddress((void**)&p_dtlo,  g_dtlo);
    cudaGetSymbolAddress((void**)&p_yhi,   g_yhi);

    const int SMEM1 = NSTAGE * 2 * TILE_BYTES;  // 81920
    const int SMEM2 = NSTAGE * 3 * TILE_BYTES;  // 122880
    cudaFuncSetAttribute(gemm_f16<1>, cudaFuncAttributeMaxDynamicSharedMemorySize, SMEM1);
    cudaFuncSetAttribute(gemm_f16<2>, cudaFuncAttributeMaxDynamicSharedMemorySize, SMEM2);

    // 0) conversions
    cvt_hilo_h<<<1024, 256>>>(x,     p_xhi,   p_xlo,  ML * D_MODEL);
    cvt_hi_h  <<<1024, 256>>>(W_in,  p_winhi,         2 * D_INNER * D_MODEL);
    cvt_hi_h  <<<256,  256>>>(W_x,   p_wxhi,          DBC_N * D_INNER);
    cvt_hi_h  <<<256,  256>>>(W_dt,  p_wdthi,         D_INNER * DT_RANK);
    cvt_hi_h  <<<1024, 256>>>(W_out, p_wouthi,        D_MODEL * D_INNER);

    // 1a) xc_raw = x @ W_in[0:2048]^T : 2-pass (A 22-bit, B fp16)
    {
        dim3 grid(D_INNER / 128, ML / 128);
        gemm_f16<2><<<grid, 256, SMEM2>>>(p_xhi, p_xlo, p_winhi, nullptr,
            D_MODEL, D_MODEL, D_MODEL, 1,
            D_INNER, 2 * D_INNER, 0, p_xz, 0, nullptr);
    }
    // 1b) z = x @ W_in[2048:4096]^T : 1-pass (silu-gate path, error tolerant)
    {
        dim3 grid(D_INNER / 128, ML / 128);
        gemm_f16<1><<<grid, 256, SMEM1>>>(p_xhi, nullptr,
            p_winhi + (size_t)D_INNER * D_MODEL, nullptr,
            D_MODEL, D_MODEL, D_MODEL, 1,
            D_INNER, 2 * D_INNER, 0, p_xz + D_INNER, 0, nullptr);
    }
    // 2) causal conv + SiLU -> xc (fp32 + fp16 hi/lo)
    {
        dim3 grid(D_INNER / 256, LENGTH / 128, BATCH);
        conv_silu_kernel<<<grid, 256>>>(conv_w, conv_b);
    }
    // 3) dbc = xc @ W_x^T : 2-pass, split-K=2 (128 CTAs), partials
    {
        dim3 grid(2, ML / 128);
        gemm_f16<2><<<grid, 256, SMEM2>>>(p_xchi, p_xclo, p_wxhi, nullptr,
            D_INNER, D_INNER, D_INNER / 2, 2,
            DBC_N, DBC_N, (size_t)ML * DBC_N, p_dbcp, 0, nullptr);
        reduce_dbc_kernel<<<1024, 256>>>();
    }
    // 4) delta = softplus(dt @ W_dt^T + b_dt) : 2-pass
    {
        dim3 grid(D_INNER / 128, ML / 128);
        gemm_f16<2><<<grid, 256, SMEM2>>>(p_dthi, p_dtlo, p_wdthi, nullptr,
            DT_RANK, DT_RANK, DT_RANK, 1,
            D_INNER, D_INNER, 0, p_delta, 2, b_dt);
    }
    // 5) selective scan -> y (fp16 hi), pipelined
    {
        dim3 grid(D_INNER / 8, BATCH);
        scan_kernel<<<grid, 32>>>(A_raw, Dvec);
    }
    // 6) out = y @ W_out^T : 1-pass
    {
        dim3 grid(D_MODEL / 128, ML / 128);
        gemm_f16<1><<<grid, 256, SMEM1>>>(p_yhi, nullptr, p_wouthi, nullptr,
            D_INNER, D_INNER, D_INNER, 1,
            D_MODEL, D_MODEL, 0, out, 0, nullptr);
    }
}

// round 16
// speedup vs baseline: 1.8596x; 1.1070x over previous
#include <cuda_runtime.h>
#include <cuda_fp16.h>
#include <math.h>
#include <stdint.h>

// Problem constants
#define D_MODEL 1024
#define D_STATE 16
#define D_CONV  4
#define D_INNER 2048
#define DT_RANK 64
#define BATCH   4
#define LENGTH  2048
#define ML      (BATCH * LENGTH)          // 8192 rows
#define DBC_N   (DT_RANK + 2 * D_STATE)   // 96

// ---------------- scratch (static __device__, no allocations) ----------------
__device__ float g_xz[ML * 2 * D_INNER];     // 8192 x 4096 (fp32)
__device__ float g_xc[ML * D_INNER];         // 8192 x 2048 (fp32, for scan)
__device__ float g_dbc[ML * DBC_N];          // 8192 x 96
__device__ float g_dbcp[2 * ML * DBC_N];     // split-K partials for dbc
__device__ float g_delta[ML * D_INNER];      // 8192 x 2048

// fp16 operand buffers
__device__ __half g_xhi [ML * D_MODEL];                       // hi only
__device__ __half g_winhi[2*D_INNER*D_MODEL];                 // hi only
__device__ __half g_wxhi[DBC_N * D_INNER];                    // hi only
__device__ __half g_wdthi[D_INNER*DT_RANK];                   // hi only
__device__ __half g_wouthi[D_MODEL*D_INNER];                  // hi only
__device__ __half g_xchi[ML * D_INNER],      g_xclo[ML * D_INNER];
__device__ __half g_dthi[ML * DT_RANK],      g_dtlo[ML * DT_RANK];
__device__ __half g_yhi [ML * D_INNER];

// ======================= low-level helpers (base sm_103 ISA only) ============
__device__ __forceinline__ uint32_t smem_to_u32(const void* p) {
    uint32_t a;
    asm("{ .reg .u64 t; cvta.to.shared.u64 t, %1; cvt.u32.u64 %0, t; }"
        : "=r"(a) : "l"(p));
    return a;
}
__device__ __forceinline__ void cp_async16(uint32_t dst, const void* src, bool pred) {
    int sz = pred ? 16 : 0;
    asm volatile("cp.async.cg.shared.global [%0], [%1], 16, %2;"
                 :: "r"(dst), "l"(src), "r"(sz) : "memory");
}
#define CP_COMMIT() asm volatile("cp.async.commit_group;" ::: "memory")
template <int N>
__device__ __forceinline__ void cp_wait() {
    asm volatile("cp.async.wait_group %0;" :: "n"(N) : "memory");
}
__device__ __forceinline__ void ldsm4(uint32_t* r, uint32_t addr) {
    asm volatile("ldmatrix.sync.aligned.m8n8.x4.shared.b16 {%0,%1,%2,%3}, [%4];"
                 : "=r"(r[0]), "=r"(r[1]), "=r"(r[2]), "=r"(r[3]) : "r"(addr));
}
__device__ __forceinline__ void mma16816(float* d, const uint32_t* a, const uint32_t* b) {
    asm volatile(
        "mma.sync.aligned.m16n8k16.row.col.f32.f16.f16.f32 "
        "{%0,%1,%2,%3}, {%4,%5,%6,%7}, {%8,%9}, {%0,%1,%2,%3};"
        : "+f"(d[0]), "+f"(d[1]), "+f"(d[2]), "+f"(d[3])
        : "r"(a[0]), "r"(a[1]), "r"(a[2]), "r"(a[3]), "r"(b[0]), "r"(b[1]));
}

// ======================= split-fp16 GEMM (mma.sync) ==========================
// C[M,N] = A[M,K] * B[N,K]^T, fp32 accumulate.
//   NPASS=1: hi*Hi                   (A fp16, B fp16)
//   NPASS=2: hi*Hi + lo*Hi           (A 22-bit, B fp16)
// CTA tile 128x128, BK=32, 8 warps (warp tile 32x64), 4-stage cp.async pipeline,
// single __syncthreads per k-block (compute-then-load ordering).
// smem rows padded to 40 fp16 (80B) -> conflict-free ldmatrix.
// Split-K: grid.x = ntiles_n * nsplit; partial C slabs csplit_stride apart.
// Modes: 0 plain fp32 C; 2 softplus(v + bias[col]).
#define TILE_BYTES  10240                  // 128 rows * 80B
#define NSTAGE 4

template <int NPASS>
__device__ __forceinline__ void load_stage(
    uint32_t sb, const __half* __restrict__ Ahi, const __half* __restrict__ Alo,
    const __half* __restrict__ Bhi,
    int lda, int ldb, int N, int m0, int n0, int kbase, int tid)
{
    constexpr int OFF_AL = TILE_BYTES;
    constexpr int OFF_BH = (NPASS >= 2 ? 2 : 1) * TILE_BYTES;
#pragma unroll
    for (int i = 0; i < 2; i++) {
        const int idx = i * 256 + tid;            // 0..511
        const int r = idx >> 2, seg = idx & 3;
        const size_t ga = (size_t)(m0 + r) * lda + kbase + seg * 8;
        const uint32_t da = sb + r * 80 + seg * 16;
        cp_async16(da, Ahi + ga, true);
        if (NPASS >= 2) cp_async16(da + OFF_AL, Alo + ga, true);
        const bool v = (n0 + r) < N;
        const size_t gb = (size_t)(n0 + (v ? r : 0)) * ldb + kbase + seg * 8;
        cp_async16(da + OFF_BH, Bhi + gb, v);
    }
}

template <int NPASS>
__global__ __launch_bounds__(256) void gemm_f16(
    const __half* __restrict__ Ahi, const __half* __restrict__ Alo,
    const __half* __restrict__ Bhi,
    int lda, int ldb, int Ksplit, int nsplit,
    int N, int ldc, size_t csplit_stride, float* __restrict__ C,
    int mode, const float* __restrict__ bias)
{
    constexpr int NT = (NPASS == 1) ? 2 : 3;
    constexpr int SB = NT * TILE_BYTES;            // bytes per stage
    constexpr int OFF_AL = TILE_BYTES;
    constexpr int OFF_BH = (NPASS >= 2 ? 2 : 1) * TILE_BYTES;
    extern __shared__ char smem[];
    const uint32_t sbase = smem_to_u32(smem);
    const int tid  = threadIdx.x;
    const int wid  = tid >> 5;
    const int lane = tid & 31;
    const int ntile = blockIdx.x / nsplit;
    const int split = blockIdx.x % nsplit;
    const int m0 = blockIdx.y * 128;
    const int n0 = ntile * 128;
    const int k0 = split * Ksplit;
    Ahi += k0; if (NPASS >= 2) Alo += k0;
    Bhi += k0;
    C += (size_t)split * csplit_stride;
    const int wm = wid >> 1;          // 0..3
    const int wn = wid & 1;           // 0..1

    // ldmatrix lane addressing
    const int lr = lane & 7, lg = lane >> 3;       // lg 0..3
    const int a_row = ((lg & 1) << 3) + lr;        // 0..15
    const int a_col = (lg >> 1) << 3;              // 0 or 8 (elements)
    const int b_row = ((lg >> 1) << 3) + lr;       // 0..15
    const int b_col = (lg & 1) << 3;               // 0 or 8

    float acc[2][8][4];
#pragma unroll
    for (int mi = 0; mi < 2; mi++)
#pragma unroll
        for (int nj = 0; nj < 8; nj++)
#pragma unroll
            for (int e = 0; e < 4; e++) acc[mi][nj][e] = 0.f;

    const int KB = Ksplit >> 5;    // k-blocks of 32

    // prologue: issue up to NSTAGE-1 stages
#pragma unroll
    for (int s = 0; s < NSTAGE - 1; s++) {
        if (s < KB) {
            load_stage<NPASS>(sbase + s * SB, Ahi, Alo, Bhi,
                              lda, ldb, N, m0, n0, s << 5, tid);
            CP_COMMIT();
        }
    }

    for (int kb = 0; kb < KB; kb++) {
        const int rem = KB - 1 - kb;
        if (rem >= 2)      cp_wait<2>();
        else if (rem == 1) cp_wait<1>();
        else               cp_wait<0>();
        __syncthreads();

        const uint32_t st = sbase + (kb & (NSTAGE - 1)) * SB;
#pragma unroll
        for (int ks = 0; ks < 2; ks++) {
            const uint32_t aoff = st + (wm * 32 + a_row) * 80 + (ks * 16 + a_col) * 2;
            const uint32_t boff = st + OFF_BH + (wn * 64 + b_row) * 80 + (ks * 16 + b_col) * 2;
            uint32_t ah[2][4], bh[4][4];
            ldsm4(ah[0], aoff);
            ldsm4(ah[1], aoff + 16 * 80);
            ldsm4(bh[0], boff);
            ldsm4(bh[1], boff + 16 * 80);
            ldsm4(bh[2], boff + 32 * 80);
            ldsm4(bh[3], boff + 48 * 80);
#pragma unroll
            for (int mi = 0; mi < 2; mi++)
#pragma unroll
                for (int nj = 0; nj < 8; nj++)
                    mma16816(acc[mi][nj], ah[mi], &bh[nj >> 1][(nj & 1) * 2]);
            if (NPASS >= 2) {
                uint32_t al[2][4];
                ldsm4(al[0], aoff + OFF_AL);
                ldsm4(al[1], aoff + OFF_AL + 16 * 80);
#pragma unroll
                for (int mi = 0; mi < 2; mi++)
#pragma unroll
                    for (int nj = 0; nj < 8; nj++)
                        mma16816(acc[mi][nj], al[mi], &bh[nj >> 1][(nj & 1) * 2]);
            }
        }

        // issue stage kb+NSTAGE-1 (its buffer (kb-1)&3 is free: all warps passed
        // this iteration's barrier, hence finished compute(kb-1))
        const int ks2 = kb + NSTAGE - 1;
        if (ks2 < KB) {
            load_stage<NPASS>(sbase + (ks2 & (NSTAGE - 1)) * SB,
                              Ahi, Alo, Bhi, lda, ldb, N, m0, n0, ks2 << 5, tid);
            CP_COMMIT();
        }
    }

    // ----- epilogue -----
    const int rbase = m0 + wm * 32 + (lane >> 2);
    const int cbase = n0 + wn * 64 + (lane & 3) * 2;
#pragma unroll
    for (int mi = 0; mi < 2; mi++) {
#pragma unroll
        for (int e = 0; e < 2; e++) {
            const int row = rbase + mi * 16 + e * 8;
#pragma unroll
            for (int nj = 0; nj < 8; nj++) {
                const int c = cbase + nj * 8;
                if (c >= N) continue;
                float v0 = acc[mi][nj][e * 2 + 0];
                float v1 = acc[mi][nj][e * 2 + 1];
                if (mode == 2) {
                    float t0 = v0 + bias[c];
                    float t1 = v1 + bias[c + 1];
                    v0 = (t0 > 20.f) ? t0 : log1pf(__expf(t0));
                    v1 = (t1 > 20.f) ? t1 : log1pf(__expf(t1));
                }
                *(float2*)(C + (size_t)row * ldc + c) = make_float2(v0, v1);
            }
        }
    }
}

// ---------------- fp32 -> fp16 conversions ----------------
__global__ __launch_bounds__(256) void cvt_hi_h(
    const float* __restrict__ src, __half* __restrict__ hi, int n)
{
    for (int i = blockIdx.x * 256 + threadIdx.x; i < n; i += gridDim.x * 256)
        hi[i] = __float2half_rn(src[i]);
}

// ---------------- split-K reduce for dbc + dt hi/lo emission -----------------
__global__ __launch_bounds__(256) void reduce_dbc_kernel()
{
    const int n = ML * DBC_N;
    for (int i = blockIdx.x * 256 + threadIdx.x; i < n; i += gridDim.x * 256) {
        const float s = g_dbcp[i] + g_dbcp[i + ML * DBC_N];
        g_dbc[i] = s;
        const int col = i % DBC_N;
        if (col < DT_RANK) {
            const int row = i / DBC_N;
            const __half h = __float2half_rn(s);
            g_dthi[row * DT_RANK + col] = h;
            g_dtlo[row * DT_RANK + col] = __float2half_rn(s - __half2float(h));
        }
    }
}

// ---------------- causal depthwise conv (k=4) + bias + SiLU ----------------
__global__ __launch_bounds__(256) void conv_silu_kernel(
    const float* __restrict__ conv_w, const float* __restrict__ conv_b)
{
    const int d  = blockIdx.x * 256 + threadIdx.x;
    const int l0 = blockIdx.y * 128;
    const int b  = blockIdx.z;

    const float w0 = conv_w[d * 4 + 0], w1 = conv_w[d * 4 + 1];
    const float w2 = conv_w[d * 4 + 2], w3 = conv_w[d * 4 + 3];
    const float bias = conv_b[d];

    const float* in = g_xz + (size_t)(b * LENGTH) * (2 * D_INNER) + d;
    float x0 = 0.f, x1 = 0.f, x2 = 0.f;
    if (l0 >= 3) {
        x0 = in[(size_t)(l0 - 3) * (2 * D_INNER)];
        x1 = in[(size_t)(l0 - 2) * (2 * D_INNER)];
        x2 = in[(size_t)(l0 - 1) * (2 * D_INNER)];
    }
    size_t o = (size_t)(b * LENGTH + l0) * D_INNER + d;
#pragma unroll 4
    for (int l = l0; l < l0 + 128; l++) {
        const float x3 = in[(size_t)l * (2 * D_INNER)];
        float v = fmaf(w0, x0, fmaf(w1, x1, fmaf(w2, x2, fmaf(w3, x3, bias))));
        v = v / (1.f + __expf(-v));
        g_xc[o] = v;
        const __half h = __float2half_rn(v);
        g_xchi[o] = h;
        g_xclo[o] = __float2half_rn(v - __half2float(h));
        o += D_INNER;
        x0 = x1; x1 = x2; x2 = x3;
    }
}

// ---------------- selective scan + D*x + silu(z) gating (pipelined) ----------
#define SCAN_CH 4
__global__ __launch_bounds__(32) void scan_kernel(
    const float* __restrict__ A_raw, const float* __restrict__ Dvec)
{
    const int lane = threadIdx.x & 31;
    const int d  = blockIdx.x * 8 + (lane & 7);
    const int n0 = (lane >> 3) * 4;
    const int b  = blockIdx.y;

    const float A0 = -expf(A_raw[(n0 + 0) * D_INNER + d]);
    const float A1 = -expf(A_raw[(n0 + 1) * D_INNER + d]);
    const float A2 = -expf(A_raw[(n0 + 2) * D_INNER + d]);
    const float A3 = -expf(A_raw[(n0 + 3) * D_INNER + d]);
    const float Dv = Dvec[d];

    const int row0 = b * LENGTH;
    const float* dp = g_delta + (size_t)row0 * D_INNER + d;
    const float* xp = g_xc    + (size_t)row0 * D_INNER + d;
    const float* zp = g_xz    + (size_t)row0 * (2 * D_INNER) + D_INNER + d;
    const float4* Bp = (const float4*)(g_dbc + (size_t)row0 * DBC_N + DT_RANK + n0);
    const float4* Cp = (const float4*)(g_dbc + (size_t)row0 * DBC_N + DT_RANK + D_STATE + n0);
    const size_t yo0 = (size_t)row0 * D_INNER + d;

    float  dlt[2][SCAN_CH], xv[2][SCAN_CH], zv[2][SCAN_CH];
    float4 Bv[2][SCAN_CH], Cv[2][SCAN_CH];

#pragma unroll
    for (int i = 0; i < SCAN_CH; i++) {
        dlt[0][i] = dp[(size_t)i * D_INNER];
        xv [0][i] = xp[(size_t)i * D_INNER];
        zv [0][i] = zp[(size_t)i * 2 * D_INNER];
        Bv [0][i] = Bp[i * (DBC_N / 4)];
        Cv [0][i] = Cp[i * (DBC_N / 4)];
    }

    float h0 = 0.f, h1 = 0.f, h2 = 0.f, h3 = 0.f;

    const int NCH = LENGTH / SCAN_CH;   // 512
#pragma unroll 2
    for (int c = 0; c < NCH; c++) {
        const int cur = c & 1, nxt = cur ^ 1;
        if (c + 1 < NCH) {
            const size_t lb = (size_t)(c + 1) * SCAN_CH;
#pragma unroll
            for (int i = 0; i < SCAN_CH; i++) {
                dlt[nxt][i] = dp[(lb + i) * D_INNER];
                xv [nxt][i] = xp[(lb + i) * D_INNER];
                zv [nxt][i] = zp[(lb + i) * 2 * D_INNER];
                Bv [nxt][i] = Bp[(lb + i) * (DBC_N / 4)];
                Cv [nxt][i] = Cp[(lb + i) * (DBC_N / 4)];
            }
        }
#pragma unroll
        for (int i = 0; i < SCAN_CH; i++) {
            const float dl = dlt[cur][i];
            const float xx = xv[cur][i];
            const float dx = dl * xx;
            const float4 B4 = Bv[cur][i];
            const float4 C4 = Cv[cur][i];
            h0 = fmaf(__expf(dl * A0), h0, B4.x * dx);
            h1 = fmaf(__expf(dl * A1), h1, B4.y * dx);
            h2 = fmaf(__expf(dl * A2), h2, B4.z * dx);
            h3 = fmaf(__expf(dl * A3), h3, B4.w * dx);
            float p = C4.x * h0 + C4.y * h1 + C4.z * h2 + C4.w * h3;
            p += __shfl_xor_sync(0xffffffffu, p, 8);
            p += __shfl_xor_sync(0xffffffffu, p, 16);
            if (n0 == 0) {
                const float zz = zv[cur][i];
                const float sz = zz / (1.f + __expf(-zz));
                const float yv = (p + Dv * xx) * sz;
                const size_t yo = yo0 + (size_t)(c * SCAN_CH + i) * D_INNER;
                g_yhi[yo] = __float2half_rn(yv);
            }
        }
    }
}

// ---------------- host launch ----------------
extern "C" void kernel_launch(void* const* d_in, const int* in_sizes, int n_in,
                              void* d_out, int out_size)
{
    const float* x      = (const float*)d_in[0];
    const float* W_in   = (const float*)d_in[1];
    const float* conv_w = (const float*)d_in[2];
    const float* conv_b = (const float*)d_in[3];
    const float* W_x    = (const float*)d_in[4];
    const float* W_dt   = (const float*)d_in[5];
    const float* b_dt   = (const float*)d_in[6];
    const float* A_raw  = (const float*)d_in[7];
    const float* Dvec   = (const float*)d_in[8];
    const float* W_out  = (const float*)d_in[9];
    float* out = (float*)d_out;

    float *p_xz, *p_dbcp, *p_delta;
    __half *p_xhi, *p_winhi, *p_wxhi;
    __half *p_wdthi, *p_wouthi;
    __half *p_xchi, *p_xclo, *p_dthi, *p_dtlo, *p_yhi;
    cudaGetSymbolAddress((void**)&p_xz,    g_xz);
    cudaGetSymbolAddress((void**)&p_dbcp,  g_dbcp);
    cudaGetSymbolAddress((void**)&p_delta, g_delta);
    cudaGetSymbolAddress((void**)&p_xhi,   g_xhi);
    cudaGetSymbolAddress((void**)&p_winhi, g_winhi);
    cudaGetSymbolAddress((void**)&p_wxhi,  g_wxhi);
    cudaGetSymbolAddress((void**)&p_wdthi, g_wdthi);
    cudaGetSymbolAddress((void**)&p_wouthi,g_wouthi);
    cudaGetSymbolAddress((void**)&p_xchi,  g_xchi);
    cudaGetSymbolAddress((void**)&p_xclo,  g_xclo);
    cudaGetSymbolAddress((void**)&p_dthi,  g_dthi);
    cudaGetSymbolAddress((void**)&p_dtlo,  g_dtlo);
    cudaGetSymbolAddress((void**)&p_yhi,   g_yhi);

    const int SMEM1 = NSTAGE * 2 * TILE_BYTES;  // 81920
    const int SMEM2 = NSTAGE * 3 * TILE_BYTES;  // 122880
    cudaFuncSetAttribute(gemm_f16<1>, cudaFuncAttributeMaxDynamicSharedMemorySize, SMEM1);
    cudaFuncSetAttribute(gemm_f16<2>, cudaFuncAttributeMaxDynamicSharedMemorySize, SMEM2);

    // 0) conversions (all hi-only now)
    cvt_hi_h<<<1024, 256>>>(x,     p_xhi,   ML * D_MODEL);
    cvt_hi_h<<<1024, 256>>>(W_in,  p_winhi, 2 * D_INNER * D_MODEL);
    cvt_hi_h<<<256,  256>>>(W_x,   p_wxhi,  DBC_N * D_INNER);
    cvt_hi_h<<<256,  256>>>(W_dt,  p_wdthi, D_INNER * DT_RANK);
    cvt_hi_h<<<1024, 256>>>(W_out, p_wouthi,D_MODEL * D_INNER);

    // 1) xz = x @ W_in^T : single 1-pass fp16 launch over N=4096
    {
        dim3 grid((2 * D_INNER) / 128, ML / 128);
        gemm_f16<1><<<grid, 256, SMEM1>>>(p_xhi, nullptr, p_winhi,
            D_MODEL, D_MODEL, D_MODEL, 1,
            2 * D_INNER, 2 * D_INNER, 0, p_xz, 0, nullptr);
    }
    // 2) causal conv + SiLU -> xc (fp32 + fp16 hi/lo)
    {
        dim3 grid(D_INNER / 256, LENGTH / 128, BATCH);
        conv_silu_kernel<<<grid, 256>>>(conv_w, conv_b);
    }
    // 3) dbc = xc @ W_x^T : 2-pass, split-K=2 (128 CTAs), partials
    {
        dim3 grid(2, ML / 128);
        gemm_f16<2><<<grid, 256, SMEM2>>>(p_xchi, p_xclo, p_wxhi,
            D_INNER, D_INNER, D_INNER / 2, 2,
            DBC_N, DBC_N, (size_t)ML * DBC_N, p_dbcp, 0, nullptr);
        reduce_dbc_kernel<<<1024, 256>>>();
    }
    // 4) delta = softplus(dt @ W_dt^T + b_dt) : 2-pass
    {
        dim3 grid(D_INNER / 128, ML / 128);
        gemm_f16<2><<<grid, 256, SMEM2>>>(p_dthi, p_dtlo, p_wdthi,
            DT_RANK, DT_RANK, DT_RANK, 1,
            D_INNER, D_INNER, 0, p_delta, 2, b_dt);
    }
    // 5) selective scan -> y (fp16 hi), pipelined
    {
        dim3 grid(D_INNER / 8, BATCH);
        scan_kernel<<<grid, 32>>>(A_raw, Dvec);
    }
    // 6) out = y @ W_out^T : 1-pass
    {
        dim3 grid(D_MODEL / 128, ML / 128);
        gemm_f16<1><<<grid, 256, SMEM1>>>(p_yhi, nullptr, p_wouthi,
            D_INNER, D_INNER, D_INNER, 1,
            D_MODEL, D_MODEL, 0, out, 0, nullptr);
    }
}